// round 13
// baseline (speedup 1.0000x reference)
#include <cuda_runtime.h>
#include <cstdint>

#define DIMX 4096      // model dim (= N_HEADS*HEAD_DIM)
#define BQ   8         // batch
#define KVD  1024      // N_KV_HEADS*HEAD_DIM
#define KS_UP 4        // k-split for up
#define KS_DN 2        // k-split for down
#define RPB  16        // rows per bcast block (R6-measured optimum)

// Scratch (allocation-free rule: __device__ globals)
__device__ float g_xp[KS_UP][BQ * KVD];   // up partials
__device__ float g_x[BQ * KVD];           // summed x [8,1024]
__device__ float g_yp[KS_DN][BQ * DIMX];  // down partials [2][8,4096]

__device__ __forceinline__ float warp_sum(float v) {
#pragma unroll
    for (int o = 16; o; o >>= 1) v += __shfl_xor_sync(0xffffffffu, v, o);
    return v;
}

// packed f32x2 FMA (Blackwell)
__device__ __forceinline__ void ffma2(unsigned long long& c,
                                      unsigned long long a,
                                      unsigned long long b) {
    asm("fma.rn.f32x2 %0, %1, %2, %0;" : "+l"(c) : "l"(a), "l"(b));
}

__device__ __forceinline__ float unpack_sum(unsigned long long p) {
    float2 f = *reinterpret_cast<float2*>(&p);
    return f.x + f.y;
}

// ---------------------------------------------------------------------------
// Kernel 1: up partials. Grid (128 j-groups, 4 k-slices) x 256.
// E slice staged in smem (LDS lat 29 vs L2 234); all 8 w4 DRAM loads
// issued up front (MLP=8/warp) via full unroll.
// ---------------------------------------------------------------------------
__global__ __launch_bounds__(256) void up_kernel(const float* __restrict__ E,
                                                 const float* __restrict__ Wup) {
    __shared__ float s_e[BQ * 1024];  // 32 KB E k-slice
    const int tid = threadIdx.x;
    const int lane = tid & 31, warp = tid >> 5;
    const int j  = blockIdx.x * 8 + warp;
    const int ks = blockIdx.y;
    const int k0 = ks * 1024;

    {
        float4* sd = reinterpret_cast<float4*>(s_e);
#pragma unroll
        for (int i = tid; i < BQ * 1024 / 4; i += 256) {
            const int b = i >> 8;      // 256 float4 per b
            const int c = i & 255;
            sd[i] = *reinterpret_cast<const float4*>(E + (size_t)b * DIMX + k0 + c * 4);
        }
    }
    __syncthreads();

    unsigned long long acc[8];
#pragma unroll
    for (int b = 0; b < 8; b++) acc[b] = 0ull;

    const float* wrow = Wup + (size_t)j * DIMX + k0;

    ulonglong2 w4[8];
#pragma unroll
    for (int it = 0; it < 8; ++it)
        w4[it] = *reinterpret_cast<const ulonglong2*>(wrow + it * 128 + lane * 4);

#pragma unroll
    for (int it = 0; it < 8; ++it) {
        const int kf = it * 128 + lane * 4;
#pragma unroll
        for (int b = 0; b < 8; b++) {
            const ulonglong2 e = *reinterpret_cast<const ulonglong2*>(s_e + b * 1024 + kf);
            ffma2(acc[b], w4[it].x, e.x);
            ffma2(acc[b], w4[it].y, e.y);
        }
    }

#pragma unroll
    for (int b = 0; b < 8; b++) {
        float s = warp_sum(unpack_sum(acc[b]));
        if (lane == 0) g_xp[ks][b * KVD + j] = s;
    }
}

// ---------------------------------------------------------------------------
// Kernel 1b: g_x = sum of 4 up partials (8192 floats). 16 blocks x 128.
// ---------------------------------------------------------------------------
__global__ __launch_bounds__(128) void sumx_kernel() {
    const int i = blockIdx.x * 128 + threadIdx.x;  // float4 index, 2048 total
    const float4 a = reinterpret_cast<const float4*>(g_xp[0])[i];
    const float4 b = reinterpret_cast<const float4*>(g_xp[1])[i];
    const float4 c = reinterpret_cast<const float4*>(g_xp[2])[i];
    const float4 d = reinterpret_cast<const float4*>(g_xp[3])[i];
    float4 r;
    r.x = (a.x + b.x) + (c.x + d.x);
    r.y = (a.y + b.y) + (c.y + d.y);
    r.z = (a.z + b.z) + (c.z + d.z);
    r.w = (a.w + b.w) + (c.w + d.w);
    reinterpret_cast<float4*>(g_x)[i] = r;
}

// ---------------------------------------------------------------------------
// Kernel 2: down partials. Grid (512 j-groups, 2 k-halves) x 256.
// Warp w computes y[:, blkx*8+w] over expanded k-half [kh*2048, +2048).
// kv fold maps the half onto x[:, kh*512 : +512] -> 16KB smem.
// w4 loads front-batched in 2 groups of 8 -> MLP=8 per warp.
// ---------------------------------------------------------------------------
__global__ __launch_bounds__(256) void down_kernel(const float* __restrict__ Wdn) {
    __shared__ float s_x[BQ * 512];  // 16 KB: x slice for this k-half
    const int tid = threadIdx.x;
    const int kh = blockIdx.y;

    {
        float4* sd = reinterpret_cast<float4*>(s_x);
#pragma unroll
        for (int i = tid; i < BQ * 512 / 4; i += 256) {
            const int b = i >> 7;          // 128 float4 per b
            const int c = i & 127;
            sd[i] = *reinterpret_cast<const float4*>(g_x + (size_t)b * KVD + kh * 512 + c * 4);
        }
    }
    __syncthreads();

    const int lane = tid & 31, warp = tid >> 5;
    const int i = blockIdx.x * 8 + warp;

    unsigned long long acc[8];
#pragma unroll
    for (int b = 0; b < 8; b++) acc[b] = 0ull;

    const float* wrow = Wdn + (size_t)i * DIMX + kh * 2048;

#pragma unroll
    for (int h = 0; h < 2; ++h) {
        // front-batch 8 weight loads (8 in flight)
        ulonglong2 w4[8];
#pragma unroll
        for (int u = 0; u < 8; ++u)
            w4[u] = *reinterpret_cast<const ulonglong2*>(
                wrow + (h * 8 + u) * 128 + lane * 4);
#pragma unroll
        for (int u = 0; u < 8; ++u) {
            const int jf = (h * 8 + u) * 128 + lane * 4;    // local expanded idx
            const int jsrc = ((jf >> 9) << 7) | (jf & 127); // folded, in [0,512)
#pragma unroll
            for (int b = 0; b < 8; b++) {
                const ulonglong2 v =
                    *reinterpret_cast<const ulonglong2*>(s_x + b * 512 + jsrc);
                ffma2(acc[b], w4[u].x, v.x);
                ffma2(acc[b], w4[u].y, v.y);
            }
        }
    }

#pragma unroll
    for (int b = 0; b < 8; b++) {
        float s = warp_sum(unpack_sum(acc[b]));
        if (lane == 0) g_yp[kh][b * DIMX + i] = s;
    }
}

// ---------------------------------------------------------------------------
// Kernel 3: broadcast. Grid 1024 blocks x 256, 16 rows/block.
// Fast path (block inside one sequence — always true since seqlens are
// multiples of 256): sequence search + y load done ONCE per block, then a
// pure streaming-store loop. Slow path kept for safety.
// ---------------------------------------------------------------------------
__global__ __launch_bounds__(256) void bcast_kernel(const int* __restrict__ seq,
                                                    float* __restrict__ out,
                                                    int nrows) {
    const int tid = threadIdx.x;

    // seqlen dtype defense: int32 expected; int64 low-word fallback
    int s[8];
#pragma unroll
    for (int i = 0; i < 8; i++) s[i] = __ldg(seq + i);
    int tot = 0;
#pragma unroll
    for (int i = 0; i < 8; i++) tot += s[i];
    if (tot != nrows) {
#pragma unroll
        for (int i = 0; i < 8; i++) s[i] = __ldg(seq + 2 * i);
    }
    int pre[9];
    pre[0] = 0;
#pragma unroll
    for (int i = 0; i < 8; i++) pre[i + 1] = pre[i] + s[i];

    const int r0 = blockIdx.x * RPB;
    int r1 = r0 + RPB;
    if (r1 > nrows) r1 = nrows;
    if (r0 >= r1) return;

    int b0 = 0, b1 = 0;
#pragma unroll
    for (int i = 0; i < 7; i++) {
        if (r0 >= pre[b0 + 1]) ++b0;
        if (r1 - 1 >= pre[b1 + 1]) ++b1;
    }

    if (b0 == b1) {
        // ---- fast path: load row slice once, then pure stores ----
        const float4* y0 = reinterpret_cast<const float4*>(g_yp[0] + b0 * DIMX);
        const float4* y1 = reinterpret_cast<const float4*>(g_yp[1] + b0 * DIMX);
        float4 v0, v1, v2, v3, a, c;
        a = y0[tid];       c = y1[tid];
        v0.x = a.x + c.x; v0.y = a.y + c.y; v0.z = a.z + c.z; v0.w = a.w + c.w;
        a = y0[tid + 256]; c = y1[tid + 256];
        v1.x = a.x + c.x; v1.y = a.y + c.y; v1.z = a.z + c.z; v1.w = a.w + c.w;
        a = y0[tid + 512]; c = y1[tid + 512];
        v2.x = a.x + c.x; v2.y = a.y + c.y; v2.z = a.z + c.z; v2.w = a.w + c.w;
        a = y0[tid + 768]; c = y1[tid + 768];
        v3.x = a.x + c.x; v3.y = a.y + c.y; v3.z = a.z + c.z; v3.w = a.w + c.w;

        float4* op = reinterpret_cast<float4*>(out + (size_t)r0 * DIMX) + tid;
#pragma unroll 4
        for (int r = r0; r < r1; ++r) {
            __stcs(op,       v0);
            __stcs(op + 256, v1);
            __stcs(op + 512, v2);
            __stcs(op + 768, v3);
            op += DIMX / 4;
        }
    } else {
        // ---- slow path: spans a sequence boundary ----
        int curb = -1;
        float4 v0, v1, v2, v3;
        for (int r = r0; r < r1; ++r) {
            int b = 0;
#pragma unroll
            for (int i = 0; i < 7; i++)
                if (r >= pre[b + 1]) ++b;
            if (b != curb) {
                const float4* y0 = reinterpret_cast<const float4*>(g_yp[0] + b * DIMX);
                const float4* y1 = reinterpret_cast<const float4*>(g_yp[1] + b * DIMX);
                float4 a, c;
                a = y0[tid];       c = y1[tid];
                v0.x = a.x + c.x; v0.y = a.y + c.y; v0.z = a.z + c.z; v0.w = a.w + c.w;
                a = y0[tid + 256]; c = y1[tid + 256];
                v1.x = a.x + c.x; v1.y = a.y + c.y; v1.z = a.z + c.z; v1.w = a.w + c.w;
                a = y0[tid + 512]; c = y1[tid + 512];
                v2.x = a.x + c.x; v2.y = a.y + c.y; v2.z = a.z + c.z; v2.w = a.w + c.w;
                a = y0[tid + 768]; c = y1[tid + 768];
                v3.x = a.x + c.x; v3.y = a.y + c.y; v3.z = a.z + c.z; v3.w = a.w + c.w;
                curb = b;
            }
            float4* op = reinterpret_cast<float4*>(out + (size_t)r * DIMX);
            __stcs(op + tid,       v0);
            __stcs(op + tid + 256, v1);
            __stcs(op + tid + 512, v2);
            __stcs(op + tid + 768, v3);
        }
    }
}

// ---------------------------------------------------------------------------
extern "C" void kernel_launch(void* const* d_in, const int* in_sizes, int n_in,
                              void* d_out, int out_size) {
    const float* E   = (const float*)d_in[0];
    const float* Wup = (const float*)d_in[1];
    const float* Wdn = (const float*)d_in[2];
    const int*   seq = (const int*)d_in[3];
    float* out = (float*)d_out;

    const int nrows = out_size / DIMX;  // 16384

    up_kernel<<<dim3(128, KS_UP), 256>>>(E, Wup);
    sumx_kernel<<<16, 128>>>();
    down_kernel<<<dim3(512, KS_DN), 256>>>(Wdn);
    bcast_kernel<<<(nrows + RPB - 1) / RPB, 256>>>(seq, out, nrows);
}

// round 14
// speedup vs baseline: 1.2164x; 1.2164x over previous
#include <cuda_runtime.h>
#include <cstdint>

#define DIMX 4096      // model dim (= N_HEADS*HEAD_DIM)
#define BQ   8         // batch
#define KVD  1024      // N_KV_HEADS*HEAD_DIM
#define KS_UP 4        // k-split for up
#define KS_DN 2        // k-split for down
#define RPB  16        // rows per bcast block (R6-measured optimum)

// Scratch (allocation-free rule: __device__ globals)
__device__ float g_xp[KS_UP][BQ * KVD];   // up partials
__device__ float g_x[BQ * KVD];           // summed x [8,1024]
__device__ float g_yp[KS_DN][BQ * DIMX];  // down partials [2][8,4096]

__device__ __forceinline__ float warp_sum(float v) {
#pragma unroll
    for (int o = 16; o; o >>= 1) v += __shfl_xor_sync(0xffffffffu, v, o);
    return v;
}

// packed f32x2 FMA (Blackwell)
__device__ __forceinline__ void ffma2(unsigned long long& c,
                                      unsigned long long a,
                                      unsigned long long b) {
    asm("fma.rn.f32x2 %0, %1, %2, %0;" : "+l"(c) : "l"(a), "l"(b));
}

__device__ __forceinline__ float unpack_sum(unsigned long long p) {
    float2 f = *reinterpret_cast<float2*>(&p);
    return f.x + f.y;
}

// ---------------------------------------------------------------------------
// Kernel 1: up partials. Grid (128 j-groups, 4 k-slices) x 256.
// E slice staged in smem (LDS lat 29 vs L2 234); all 8 w4 DRAM loads
// issued up front (MLP=8/warp) via full unroll.  [R11-measured form]
// ---------------------------------------------------------------------------
__global__ __launch_bounds__(256) void up_kernel(const float* __restrict__ E,
                                                 const float* __restrict__ Wup) {
    __shared__ float s_e[BQ * 1024];  // 32 KB E k-slice
    const int tid = threadIdx.x;
    const int lane = tid & 31, warp = tid >> 5;
    const int j  = blockIdx.x * 8 + warp;
    const int ks = blockIdx.y;
    const int k0 = ks * 1024;

    {
        float4* sd = reinterpret_cast<float4*>(s_e);
#pragma unroll
        for (int i = tid; i < BQ * 1024 / 4; i += 256) {
            const int b = i >> 8;      // 256 float4 per b
            const int c = i & 255;
            sd[i] = *reinterpret_cast<const float4*>(E + (size_t)b * DIMX + k0 + c * 4);
        }
    }
    __syncthreads();

    unsigned long long acc[8];
#pragma unroll
    for (int b = 0; b < 8; b++) acc[b] = 0ull;

    const float* wrow = Wup + (size_t)j * DIMX + k0;

    ulonglong2 w4[8];
#pragma unroll
    for (int it = 0; it < 8; ++it)
        w4[it] = *reinterpret_cast<const ulonglong2*>(wrow + it * 128 + lane * 4);

#pragma unroll
    for (int it = 0; it < 8; ++it) {
        const int kf = it * 128 + lane * 4;
#pragma unroll
        for (int b = 0; b < 8; b++) {
            const ulonglong2 e = *reinterpret_cast<const ulonglong2*>(s_e + b * 1024 + kf);
            ffma2(acc[b], w4[it].x, e.x);
            ffma2(acc[b], w4[it].y, e.y);
        }
    }

#pragma unroll
    for (int b = 0; b < 8; b++) {
        float s = warp_sum(unpack_sum(acc[b]));
        if (lane == 0) g_xp[ks][b * KVD + j] = s;
    }
}

// ---------------------------------------------------------------------------
// Kernel 1b: g_x = sum of 4 up partials (8192 floats). 16 blocks x 128.
// ---------------------------------------------------------------------------
__global__ __launch_bounds__(128) void sumx_kernel() {
    const int i = blockIdx.x * 128 + threadIdx.x;  // float4 index, 2048 total
    const float4 a = reinterpret_cast<const float4*>(g_xp[0])[i];
    const float4 b = reinterpret_cast<const float4*>(g_xp[1])[i];
    const float4 c = reinterpret_cast<const float4*>(g_xp[2])[i];
    const float4 d = reinterpret_cast<const float4*>(g_xp[3])[i];
    float4 r;
    r.x = (a.x + b.x) + (c.x + d.x);
    r.y = (a.y + b.y) + (c.y + d.y);
    r.z = (a.z + b.z) + (c.z + d.z);
    r.w = (a.w + b.w) + (c.w + d.w);
    reinterpret_cast<float4*>(g_x)[i] = r;
}

// ---------------------------------------------------------------------------
// Kernel 2: down partials. Grid (512 j-groups, 2 k-halves) x 256.
// Warp w computes y[:, blkx*8+w] over expanded k-half [kh*2048, +2048).
// kv fold maps the half onto x[:, kh*512 : +512] -> 16KB smem.
// [R11-measured form: interleaved (paced) unroll-4 mainloop]
// ---------------------------------------------------------------------------
__global__ __launch_bounds__(256) void down_kernel(const float* __restrict__ Wdn) {
    __shared__ float s_x[BQ * 512];  // 16 KB: x slice for this k-half
    const int tid = threadIdx.x;
    const int kh = blockIdx.y;

    {
        float4* sd = reinterpret_cast<float4*>(s_x);
#pragma unroll
        for (int i = tid; i < BQ * 512 / 4; i += 256) {
            const int b = i >> 7;          // 128 float4 per b
            const int c = i & 127;
            sd[i] = *reinterpret_cast<const float4*>(g_x + (size_t)b * KVD + kh * 512 + c * 4);
        }
    }
    __syncthreads();

    const int lane = tid & 31, warp = tid >> 5;
    const int i = blockIdx.x * 8 + warp;

    unsigned long long acc[8];
#pragma unroll
    for (int b = 0; b < 8; b++) acc[b] = 0ull;

    const float* wrow = Wdn + (size_t)i * DIMX + kh * 2048;

#pragma unroll 4
    for (int it = 0; it < 16; ++it) {
        const int jf = it * 128 + lane * 4;                 // local expanded idx
        const int jsrc = ((jf >> 9) << 7) | (jf & 127);     // folded, in [0,512)
        const ulonglong2 w4 = *reinterpret_cast<const ulonglong2*>(wrow + jf);
        ulonglong2 v[8];
#pragma unroll
        for (int b = 0; b < 8; b++)
            v[b] = *reinterpret_cast<const ulonglong2*>(s_x + b * 512 + jsrc);
#pragma unroll
        for (int b = 0; b < 8; b++) {
            ffma2(acc[b], w4.x, v[b].x);
            ffma2(acc[b], w4.y, v[b].y);
        }
    }

#pragma unroll
    for (int b = 0; b < 8; b++) {
        float s = warp_sum(unpack_sum(acc[b]));
        if (lane == 0) g_yp[kh][b * DIMX + i] = s;
    }
}

// ---------------------------------------------------------------------------
// Kernel 3: broadcast. [R6-measured form, 45.7us]
// Grid: 1024 blocks x 256, 16 rows/block. Per-row sequence search with
// register caching of the y slice; the per-row ALU interleave PACES the
// store stream and avoids L1tex store-queue overflow (R13 evidence).
// Sums the 2 down partials on each y reload. Streaming stores.
// ---------------------------------------------------------------------------
__global__ __launch_bounds__(256) void bcast_kernel(const int* __restrict__ seq,
                                                    float* __restrict__ out,
                                                    int nrows) {
    const int tid = threadIdx.x;

    // seqlen dtype defense: int32 expected; int64 low-word fallback
    int s[8];
#pragma unroll
    for (int i = 0; i < 8; i++) s[i] = __ldg(seq + i);
    int tot = 0;
#pragma unroll
    for (int i = 0; i < 8; i++) tot += s[i];
    if (tot != nrows) {
#pragma unroll
        for (int i = 0; i < 8; i++) s[i] = __ldg(seq + 2 * i);
    }
    int pre[9];
    pre[0] = 0;
#pragma unroll
    for (int i = 0; i < 8; i++) pre[i + 1] = pre[i] + s[i];

    const int r0 = blockIdx.x * RPB;
    int r1 = r0 + RPB;
    if (r1 > nrows) r1 = nrows;

    int curb = -1;
    float4 v0, v1, v2, v3;

    for (int r = r0; r < r1; ++r) {
        int b = 0;
#pragma unroll
        for (int i = 0; i < 7; i++)
            if (r >= pre[b + 1]) ++b;
        if (b != curb) {
            const float4* y0 = reinterpret_cast<const float4*>(g_yp[0] + b * DIMX);
            const float4* y1 = reinterpret_cast<const float4*>(g_yp[1] + b * DIMX);
            float4 a, c;
            a = y0[tid];       c = y1[tid];
            v0.x = a.x + c.x; v0.y = a.y + c.y; v0.z = a.z + c.z; v0.w = a.w + c.w;
            a = y0[tid + 256]; c = y1[tid + 256];
            v1.x = a.x + c.x; v1.y = a.y + c.y; v1.z = a.z + c.z; v1.w = a.w + c.w;
            a = y0[tid + 512]; c = y1[tid + 512];
            v2.x = a.x + c.x; v2.y = a.y + c.y; v2.z = a.z + c.z; v2.w = a.w + c.w;
            a = y0[tid + 768]; c = y1[tid + 768];
            v3.x = a.x + c.x; v3.y = a.y + c.y; v3.z = a.z + c.z; v3.w = a.w + c.w;
            curb = b;
        }
        float4* op = reinterpret_cast<float4*>(out + (size_t)r * DIMX);
        __stcs(op + tid,       v0);
        __stcs(op + tid + 256, v1);
        __stcs(op + tid + 512, v2);
        __stcs(op + tid + 768, v3);
    }
}

// ---------------------------------------------------------------------------
extern "C" void kernel_launch(void* const* d_in, const int* in_sizes, int n_in,
                              void* d_out, int out_size) {
    const float* E   = (const float*)d_in[0];
    const float* Wup = (const float*)d_in[1];
    const float* Wdn = (const float*)d_in[2];
    const int*   seq = (const int*)d_in[3];
    float* out = (float*)d_out;

    const int nrows = out_size / DIMX;  // 16384

    up_kernel<<<dim3(128, KS_UP), 256>>>(E, Wup);
    sumx_kernel<<<16, 128>>>();
    down_kernel<<<dim3(512, KS_DN), 256>>>(Wdn);
    bcast_kernel<<<(nrows + RPB - 1) / RPB, 256>>>(seq, out, nrows);
}